// round 5
// baseline (speedup 1.0000x reference)
#include <cuda_runtime.h>
#include <mma.h>
#include <cstdint>
#include <cstddef>

using namespace nvcuda;

// ---------------------------------------------------------------------------
// B=16, T=64, HW=7 (49), D=768, N=12 heads, C=64, EPS=1e-5
// Fused formulation:
//   Weff[hw*768+k, s*768+n*64+d] = sum_c W_qkv[k, s*768+n*64+c] * Wp_s[d,c,hw]
//   qkv_pooled[bt, s*768+n*64+d] = sum_{hw,k} x[bt, hw*768+k] * Weff[...]
// -> ONE GEMM (1024 x 2304 x 37632), epilogue = +bias, LayerNorm over d.
// ---------------------------------------------------------------------------
#define BT     1024
#define D3     2304
#define KBIG   37632        // 49*768
#define NHEAD  12
#define HW2    49

// ---------------------------------------------------------------------------
// Device scratch (statics; no runtime allocation)
// ---------------------------------------------------------------------------
__device__ float g_weff[(size_t)KBIG * D3];    // 346.8 MB
__device__ float g_wpT[3 * HW2 * 64 * 64];     // Wp transposed [s][hw][c][d]
__device__ float g_qb[BT * 768];               // (B,N,T,C) post-LN q
__device__ float g_kb[BT * 768];
__device__ float g_vb[BT * 768];
__device__ float g_att[BT * 768];              // (B,T,768) attention out

// ---------------------------------------------------------------------------
// tf32 pre-round (round-to-nearest; values become exact tf32 bit patterns)
// ---------------------------------------------------------------------------
__device__ __forceinline__ float f2tf(float x) {
    uint32_t u;
    asm("cvt.rna.tf32.f32 %0, %1;" : "=r"(u) : "f"(x));
    return __uint_as_float(u);
}
__device__ __forceinline__ float4 cvt4(float4 v) {
    float4 w;
    w.x = f2tf(v.x); w.y = f2tf(v.y); w.z = f2tf(v.z); w.w = f2tf(v.w);
    return w;
}

typedef wmma::fragment<wmma::matrix_a, 16, 16, 8, wmma::precision::tf32, wmma::row_major> FragA;
typedef wmma::fragment<wmma::matrix_b, 16, 16, 8, wmma::precision::tf32, wmma::row_major> FragB;
typedef wmma::fragment<wmma::accumulator, 16, 16, 8, float> FragC;

// ---------------------------------------------------------------------------
// K00: transpose Wp (d,c,hw) -> g_wpT[s][hw][c][d]
// ---------------------------------------------------------------------------
__global__ void __launch_bounds__(256) transpose_wp_kernel(
    const float* __restrict__ wq, const float* __restrict__ wk, const float* __restrict__ wv)
{
    int idx = blockIdx.x * 256 + threadIdx.x;
    if (idx >= 3 * HW2 * 4096) return;
    int s = idx / (HW2 * 4096);
    int r = idx - s * (HW2 * 4096);     // (hw*64 + c)*64 + d
    int d  = r & 63;
    int c  = (r >> 6) & 63;
    int hw = r >> 12;
    const float* w = (s == 0) ? wq : (s == 1) ? wk : wv;
    g_wpT[idx] = f2tf(w[d * (64 * HW2) + c * HW2 + hw]);
}

// ---------------------------------------------------------------------------
// K0: Weff precompute. Block per (m-tile 128, (s,hw,n)):
//     out[k,d] = sum_c W_qkv[k, coloff+c] * wpT[s][hw][c][d]   (128x64, K=64)
// ---------------------------------------------------------------------------
__global__ void __launch_bounds__(256) weff_kernel(const float* __restrict__ Wqkv)
{
    __shared__ float As[128][36];
    __shared__ float Bs[32][72];

    const int tid = threadIdx.x, warp = tid >> 5;
    const int y = blockIdx.y;
    const int s = y / (HW2 * NHEAD);
    const int rem = y - s * (HW2 * NHEAD);
    const int hw = rem / NHEAD;
    const int n  = rem - hw * NHEAD;
    const int m0 = blockIdx.x * 128;
    const int coloff = s * 768 + n * 64;
    const float* wpT = g_wpT + (size_t)(s * HW2 + hw) * 4096;
    const int wm = (warp >> 1) * 32;   // 0..96
    const int wn = (warp & 1) * 32;    // 0/32

    FragC acc[2][2];
#pragma unroll
    for (int i = 0; i < 2; i++)
#pragma unroll
        for (int j = 0; j < 2; j++) wmma::fill_fragment(acc[i][j], 0.f);

#pragma unroll
    for (int kt = 0; kt < 2; kt++) {
#pragma unroll
        for (int it = 0; it < 4; it++) {
            int idx = tid + it * 256;
            int r = idx >> 3, q = (idx & 7) << 2;
            float4 v = *reinterpret_cast<const float4*>(
                Wqkv + (size_t)(m0 + r) * D3 + coloff + kt * 32 + q);
            *reinterpret_cast<float4*>(&As[r][q]) = cvt4(v);
        }
#pragma unroll
        for (int it = 0; it < 2; it++) {
            int idx = tid + it * 256;
            int rr = idx >> 4, dd = (idx & 15) << 2;
            // already tf32-rounded in K00
            *reinterpret_cast<float4*>(&Bs[rr][dd]) =
                *reinterpret_cast<const float4*>(wpT + (kt * 32 + rr) * 64 + dd);
        }
        __syncthreads();

#pragma unroll
        for (int kk = 0; kk < 4; kk++) {
            FragA af[2];
            FragB bf[2];
#pragma unroll
            for (int i = 0; i < 2; i++)
                wmma::load_matrix_sync(af[i], &As[wm + i * 16][kk * 8], 36);
#pragma unroll
            for (int j = 0; j < 2; j++)
                wmma::load_matrix_sync(bf[j], &Bs[kk * 8][wn + j * 16], 72);
#pragma unroll
            for (int i = 0; i < 2; i++)
#pragma unroll
                for (int j = 0; j < 2; j++)
                    wmma::mma_sync(acc[i][j], af[i], bf[j], acc[i][j]);
        }
        __syncthreads();
    }

#pragma unroll
    for (int i = 0; i < 2; i++)
#pragma unroll
        for (int j = 0; j < 2; j++) {
            float* dst = g_weff +
                (size_t)(hw * 768 + m0 + wm + i * 16) * D3 + coloff + wn + j * 16;
            wmma::store_matrix_sync(dst, acc[i][j], D3, wmma::mem_row_major);
        }
}

// ---------------------------------------------------------------------------
// K1: the big fused GEMM (1024 x 2304 x 37632) + bias + LayerNorm epilogue.
// 128x128 CTA tiles, k32 steps, register-prefetch double buffering.
// grid (18, 8) = 144 CTAs = one wave. Dynamic smem (Cs is 128x132).
// ---------------------------------------------------------------------------
#define KTILES (KBIG / 32)   // 1176
#define K1_SMEM_FLOATS (128 * 132)          // Cs; >= As(4608)+Bs(4352)=8960
#define K1_SMEM_BYTES  (K1_SMEM_FLOATS * 4) // 67584

__global__ void __launch_bounds__(256, 1) qkv_pool_ln_kernel(
    const float* __restrict__ x,
    const float* __restrict__ bq, const float* __restrict__ bk, const float* __restrict__ bv,
    const float* __restrict__ gq, const float* __restrict__ gk, const float* __restrict__ gv,
    const float* __restrict__ eq, const float* __restrict__ ek, const float* __restrict__ ev)
{
    extern __shared__ float smem[];
    float (*As)[36]  = reinterpret_cast<float(*)[36]>(smem);
    float (*Bs)[136] = reinterpret_cast<float(*)[136]>(smem + 4608);
    float (*Cs)[132] = reinterpret_cast<float(*)[132]>(smem);   // reused post-loop

    const int tid = threadIdx.x, warp = tid >> 5;
    const int m0 = blockIdx.y * 128, n0 = blockIdx.x * 128;
    const int wm = (warp >> 2) * 64, wn = (warp & 3) * 32;

    const int ar0 = tid >> 3;             // + it*32
    const int aq  = (tid & 7) << 2;
    const int br0 = tid >> 5;             // + it*8
    const int bq4 = (tid & 31) << 2;

    const float* Abase = x + (size_t)(m0 + ar0) * KBIG + aq;
    const float* Bbase = g_weff + (size_t)br0 * D3 + n0 + bq4;

    FragC acc[4][2];
#pragma unroll
    for (int i = 0; i < 4; i++)
#pragma unroll
        for (int j = 0; j < 2; j++) wmma::fill_fragment(acc[i][j], 0.f);

    float4 ra[4], rb[4];
#pragma unroll
    for (int it = 0; it < 4; it++) {
        ra[it] = *reinterpret_cast<const float4*>(Abase + (size_t)(it * 32) * KBIG);
        rb[it] = *reinterpret_cast<const float4*>(Bbase + (size_t)(it * 8) * D3);
    }
#pragma unroll
    for (int it = 0; it < 4; it++) {
        *reinterpret_cast<float4*>(&As[ar0 + it * 32][aq]) = cvt4(ra[it]);
        *reinterpret_cast<float4*>(&Bs[br0 + it * 8][bq4]) = rb[it];  // weff pre-rounded
    }
    __syncthreads();

#pragma unroll 1
    for (int kt = 0; kt < KTILES; kt++) {
        if (kt + 1 < KTILES) {
#pragma unroll
            for (int it = 0; it < 4; it++) {
                ra[it] = *reinterpret_cast<const float4*>(
                    Abase + (size_t)(it * 32) * KBIG + (kt + 1) * 32);
                rb[it] = *reinterpret_cast<const float4*>(
                    Bbase + (size_t)((kt + 1) * 32 + it * 8) * D3);
            }
        }
#pragma unroll
        for (int kk = 0; kk < 4; kk++) {
            FragA af[4];
            FragB bf[2];
#pragma unroll
            for (int i = 0; i < 4; i++)
                wmma::load_matrix_sync(af[i], &As[wm + i * 16][kk * 8], 36);
#pragma unroll
            for (int j = 0; j < 2; j++)
                wmma::load_matrix_sync(bf[j], &Bs[kk * 8][wn + j * 16], 136);
#pragma unroll
            for (int i = 0; i < 4; i++)
#pragma unroll
                for (int j = 0; j < 2; j++)
                    wmma::mma_sync(acc[i][j], af[i], bf[j], acc[i][j]);
        }
        __syncthreads();
        if (kt + 1 < KTILES) {
#pragma unroll
            for (int it = 0; it < 4; it++) {
                *reinterpret_cast<float4*>(&As[ar0 + it * 32][aq]) = cvt4(ra[it]);
                *reinterpret_cast<float4*>(&Bs[br0 + it * 8][bq4]) = rb[it];
            }
            __syncthreads();
        }
    }

    // ---- stage tile to smem (full 128x128!), then bias + LayerNorm ----
#pragma unroll
    for (int i = 0; i < 4; i++)
#pragma unroll
        for (int j = 0; j < 2; j++)
            wmma::store_matrix_sync(&Cs[wm + i * 16][wn + j * 16], acc[i][j],
                                    132, wmma::mem_row_major);
    __syncthreads();

    {
        const int r  = tid >> 1;         // 0..127 tile row
        const int hh = tid & 1;          // which 64-col head half
        const int s  = n0 / 768;
        const int nh = ((n0 - s * 768) >> 6) + hh;
        const float* bias = (s == 0) ? bq : (s == 1) ? bk : bv;
        const float* gam  = (s == 0) ? gq : (s == 1) ? gk : gv;
        const float* bet  = (s == 0) ? eq : (s == 1) ? ek : ev;
        float* outp       = (s == 0) ? g_qb : (s == 1) ? g_kb : g_vb;
        const int c0 = hh << 6;

        float mu = 0.f;
#pragma unroll
        for (int d = 0; d < 64; d++) mu += Cs[r][c0 + d] + bias[d];
        mu *= (1.f / 64.f);
        float var = 0.f;
#pragma unroll
        for (int d = 0; d < 64; d++) {
            float v = Cs[r][c0 + d] + bias[d] - mu;
            var += v * v;
        }
        var *= (1.f / 64.f);
        const float rs = rsqrtf(var + 1e-5f);

        const int bt = m0 + r;
        const int b = bt >> 6, t = bt & 63;
        const size_t obase = (((size_t)b * NHEAD + nh) * 64 + t) * 64;
#pragma unroll
        for (int d = 0; d < 64; d++) {
            float v = (Cs[r][c0 + d] + bias[d] - mu) * rs;
            outp[obase + d] = v * gam[d] + bet[d];
        }
    }
}

// ---------------------------------------------------------------------------
// K3: fused attention per (b,n): scores = 0.125*q@k^T + q@Rt^T, softmax,
// out = attn@v + q  ->  g_att (B,T,768)
// ---------------------------------------------------------------------------
#define ATTN_SMEM_FLOATS (3 * 64 * 65 + 127 * 65 + 64 * 65)
#define ATTN_SMEM_BYTES  (ATTN_SMEM_FLOATS * 4)

__global__ void __launch_bounds__(256) attn_kernel(const float* __restrict__ rel)
{
    extern __shared__ float sm[];
    float (*qs)[65] = reinterpret_cast<float(*)[65]>(sm);
    float (*ks)[65] = reinterpret_cast<float(*)[65]>(sm + 4160);
    float (*vs)[65] = reinterpret_cast<float(*)[65]>(sm + 8320);
    float (*rt)[65] = reinterpret_cast<float(*)[65]>(sm + 12480);
    float (*ss)[65] = reinterpret_cast<float(*)[65]>(sm + 12480 + 127 * 65);

    const int bn = blockIdx.x;
    const int tid = threadIdx.x;
    const size_t base = (size_t)bn * 4096;

    for (int idx = tid; idx < 4096; idx += 256) {
        int t = idx >> 6, c = idx & 63;
        qs[t][c] = g_qb[base + idx];
        ks[t][c] = g_kb[base + idx];
        vs[t][c] = g_vb[base + idx];
    }
    for (int idx = tid; idx < 127 * 64; idx += 256) {
        rt[idx >> 6][idx & 63] = rel[idx];
    }
    __syncthreads();

    const int u = tid & 63, tq = tid >> 6;
#pragma unroll 1
    for (int p = 0; p < 16; p++) {
        int t = p * 4 + tq;
        const float* rrow = rt[t - u + 63];
        float a1 = 0.f, a2 = 0.f;
#pragma unroll
        for (int c = 0; c < 64; c++) {
            float qv = qs[t][c];
            a1 += qv * ks[u][c];
            a2 += qv * rrow[c];
        }
        ss[t][u] = 0.125f * a1 + a2;
    }
    __syncthreads();

    if (tid < 64) {
        const int t = tid;
        float mx = -1e30f;
#pragma unroll 1
        for (int uu = 0; uu < 64; uu++) mx = fmaxf(mx, ss[t][uu]);
        float sum = 0.f;
#pragma unroll 1
        for (int uu = 0; uu < 64; uu++) {
            float e = __expf(ss[t][uu] - mx);
            ss[t][uu] = e;
            sum += e;
        }
        float inv = 1.f / sum;
#pragma unroll 1
        for (int uu = 0; uu < 64; uu++) ss[t][uu] *= inv;
    }
    __syncthreads();

    const int b = bn / NHEAD, nh = bn - b * NHEAD;
#pragma unroll 1
    for (int p = 0; p < 16; p++) {
        int t = p * 4 + tq;
        float o = qs[t][u];
#pragma unroll
        for (int uu = 0; uu < 64; uu++) o += ss[t][uu] * vs[uu][u];
        g_att[(size_t)(b * 64 + t) * 768 + nh * 64 + u] = o;
    }
}

// ---------------------------------------------------------------------------
// K4: output projection (1024 x 768 x 768) + bias
// ---------------------------------------------------------------------------
__global__ void __launch_bounds__(256) proj_kernel(
    const float* __restrict__ B, const float* __restrict__ bias, float* __restrict__ C)
{
    extern __shared__ float smem[];
    float (*As)[36]  = reinterpret_cast<float(*)[36]>(smem);
    float (*Bs)[136] = reinterpret_cast<float(*)[136]>(smem + 4608);
    float (*Cs)[132] = reinterpret_cast<float(*)[132]>(smem);

    const int tid = threadIdx.x, warp = tid >> 5;
    const int m0 = blockIdx.y * 128, n0 = blockIdx.x * 128;
    const int wm = (warp >> 2) * 64, wn = (warp & 3) * 32;

    FragC acc[4][2];
#pragma unroll
    for (int i = 0; i < 4; i++)
#pragma unroll
        for (int j = 0; j < 2; j++) wmma::fill_fragment(acc[i][j], 0.f);

#pragma unroll 1
    for (int kt = 0; kt < 24; kt++) {
#pragma unroll
        for (int it = 0; it < 4; it++) {
            int idx = tid + it * 256;
            int r = idx >> 3, q = (idx & 7) << 2;
            float4 v = *reinterpret_cast<const float4*>(
                g_att + (size_t)(m0 + r) * 768 + kt * 32 + q);
            *reinterpret_cast<float4*>(&As[r][q]) = cvt4(v);
        }
#pragma unroll
        for (int it = 0; it < 4; it++) {
            int idx = tid + it * 256;
            int r = idx >> 5, q = (idx & 31) << 2;
            float4 v = *reinterpret_cast<const float4*>(
                B + (size_t)(kt * 32 + r) * 768 + n0 + q);
            *reinterpret_cast<float4*>(&Bs[r][q]) = cvt4(v);
        }
        __syncthreads();

#pragma unroll
        for (int kk = 0; kk < 4; kk++) {
            FragA af[4];
            FragB bf[2];
#pragma unroll
            for (int i = 0; i < 4; i++)
                wmma::load_matrix_sync(af[i], &As[wm + i * 16][kk * 8], 36);
#pragma unroll
            for (int j = 0; j < 2; j++)
                wmma::load_matrix_sync(bf[j], &Bs[kk * 8][wn + j * 16], 136);
#pragma unroll
            for (int i = 0; i < 4; i++)
#pragma unroll
                for (int j = 0; j < 2; j++)
                    wmma::mma_sync(acc[i][j], af[i], bf[j], acc[i][j]);
        }
        __syncthreads();
    }

#pragma unroll
    for (int i = 0; i < 4; i++)
#pragma unroll
        for (int j = 0; j < 2; j++)
            wmma::store_matrix_sync(&Cs[wm + i * 16][wn + j * 16], acc[i][j],
                                    132, wmma::mem_row_major);
    __syncthreads();

    {
        const int r = tid >> 1;
        const int c0 = (tid & 1) << 6;
#pragma unroll
        for (int d = 0; d < 64; d++) {
            int col = c0 + d;
            C[(size_t)(m0 + r) * 768 + n0 + col] = Cs[r][col] + bias[n0 + col];
        }
    }
}

// ---------------------------------------------------------------------------
// Orchestration
// ---------------------------------------------------------------------------
extern "C" void kernel_launch(void* const* d_in, const int* in_sizes, int n_in,
                              void* d_out, int out_size)
{
    const float* x      = (const float*)d_in[0];
    const float* W_qkv  = (const float*)d_in[1];
    const float* Wpq    = (const float*)d_in[2];
    const float* bpq    = (const float*)d_in[3];
    const float* Wpk    = (const float*)d_in[4];
    const float* bpk    = (const float*)d_in[5];
    const float* Wpv    = (const float*)d_in[6];
    const float* bpv    = (const float*)d_in[7];
    const float* g_q    = (const float*)d_in[8];
    const float* be_q   = (const float*)d_in[9];
    const float* g_k    = (const float*)d_in[10];
    const float* be_k   = (const float*)d_in[11];
    const float* g_v    = (const float*)d_in[12];
    const float* be_v   = (const float*)d_in[13];
    const float* rel    = (const float*)d_in[14];
    const float* W_proj = (const float*)d_in[15];
    const float* b_proj = (const float*)d_in[16];
    float* out = (float*)d_out;

    cudaFuncSetAttribute(qkv_pool_ln_kernel,
                         cudaFuncAttributeMaxDynamicSharedMemorySize, K1_SMEM_BYTES);
    cudaFuncSetAttribute(proj_kernel,
                         cudaFuncAttributeMaxDynamicSharedMemorySize, K1_SMEM_BYTES);
    cudaFuncSetAttribute(attn_kernel,
                         cudaFuncAttributeMaxDynamicSharedMemorySize, ATTN_SMEM_BYTES);

    // K00: tiny Wp transpose (+ tf32 pre-round)
    transpose_wp_kernel<<<(3 * HW2 * 4096 + 255) / 256, 256>>>(Wpq, Wpk, Wpv);

    // K0: Weff precompute (batched 128x64x64 tf32 GEMMs)
    weff_kernel<<<dim3(6, 3 * HW2 * NHEAD), 256>>>(W_qkv);

    // K1: fused qkv+pool GEMM + bias + LayerNorm (one wave of 144 CTAs)
    qkv_pool_ln_kernel<<<dim3(D3 / 128, BT / 128), 256, K1_SMEM_BYTES>>>(
        x, bpq, bpk, bpv, g_q, g_k, g_v, be_q, be_k, be_v);

    // K3: attention per (b,n)
    attn_kernel<<<16 * NHEAD, 256, ATTN_SMEM_BYTES>>>(rel);

    // K4: output projection + bias
    proj_kernel<<<dim3(768 / 128, BT / 128), 256, K1_SMEM_BYTES>>>(
        W_proj, b_proj, out);
}

// round 8
// speedup vs baseline: 1.8535x; 1.8535x over previous
#include <cuda_runtime.h>
#include <mma.h>
#include <cstdint>
#include <cstddef>

using namespace nvcuda;

// ---------------------------------------------------------------------------
// B=16, T=64, HW=7 (49), D=768, N=12 heads, C=64, EPS=1e-5
//   WeffT[s*768+n*64+d, hw*768+k] = sum_c W_qkv[k, s*768+n*64+c]*Wp_s[d,c,hw]
//   qkv_pooled[bt, nd] = sum_kk x[bt, kk] * WeffT[nd, kk]
// -> ONE GEMM (1024 x 2304 x 37632), epilogue bias+LayerNorm.
// K1 has TWO bodies selected at compile time per gencode pass:
//   - tcgen05 tf32 SS (arch-accelerated sm_103a/sm_100a passes)
//   - wmma HMMA tf32 (plain compute_103 pass; known-good round-5 structure)
// ---------------------------------------------------------------------------
#define BT     1024
#define D3     2304
#define KBIG   37632        // 49*768
#define NHEAD  12
#define HW2    49
#define KTILES (KBIG / 32)  // 1176

#if defined(__CUDA_ARCH_FEAT_SM103_ALL) || defined(__CUDA_ARCH_FEAT_SM100_ALL) || defined(__CUDA_ARCH_FEAT_SM101_ALL)
#define HAS_TCGEN05 1
#else
#define HAS_TCGEN05 0
#endif

// ---------------------------------------------------------------------------
// Device scratch (statics; no runtime allocation)
// ---------------------------------------------------------------------------
__device__ float g_weffT[(size_t)D3 * KBIG];   // [n_global][k_global], 346.8 MB
__device__ float g_wpT[3 * HW2 * 64 * 64];     // Wp transposed [s][hw][c][d]
__device__ float g_qb[BT * 768];               // (B,N,T,C) post-LN q
__device__ float g_kb[BT * 768];
__device__ float g_vb[BT * 768];
__device__ float g_att[BT * 768];              // (B,T,768) attention out

// ---------------------------------------------------------------------------
// Common helpers
// ---------------------------------------------------------------------------
__device__ __forceinline__ float f2tf(float x) {
    uint32_t u;
    asm("cvt.rna.tf32.f32 %0, %1;" : "=r"(u) : "f"(x));
    return __uint_as_float(u);
}
__device__ __forceinline__ float4 cvt4(float4 v) {
    float4 w;
    w.x = f2tf(v.x); w.y = f2tf(v.y); w.z = f2tf(v.z); w.w = f2tf(v.w);
    return w;
}

typedef wmma::fragment<wmma::matrix_a, 16, 16, 8, wmma::precision::tf32, wmma::row_major> FragA;
typedef wmma::fragment<wmma::matrix_b, 16, 16, 8, wmma::precision::tf32, wmma::row_major> FragB;
typedef wmma::fragment<wmma::matrix_b, 16, 16, 8, wmma::precision::tf32, wmma::col_major> FragBc;
typedef wmma::fragment<wmma::accumulator, 16, 16, 8, float> FragC;

__device__ __forceinline__ uint32_t elect_one_pred() {
    uint32_t pred;
    asm volatile(
        "{\n\t.reg .pred p;\n\t"
        "elect.sync _|p, 0xFFFFFFFF;\n\t"
        "selp.b32 %0, 1, 0, p;\n\t}"
        : "=r"(pred));
    return pred;
}
__device__ __forceinline__ uint32_t smem_to_u32(const void* p) {
    uint32_t a;
    asm("{ .reg .u64 t; cvta.to.shared.u64 t, %1; cvt.u32.u64 %0, t; }"
        : "=r"(a) : "l"(p));
    return a;
}

#define MBARRIER_INIT(addr, cnt) \
    asm volatile("mbarrier.init.shared.b64 [%0], %1;" :: "r"(addr), "r"(cnt) : "memory")

#define MBARRIER_WAIT_PARITY(addr, par) do {                                   \
    uint32_t _m = (addr), _p = (par), _d;                                      \
    asm volatile(                                                              \
        "{\n\t.reg .pred p;\n\t"                                               \
        "mbarrier.try_wait.parity.acquire.cta.shared::cta.b64 p, [%1], %2;\n\t"\
        "selp.b32 %0, 1, 0, p;\n\t}"                                           \
        : "=r"(_d) : "r"(_m), "r"(_p) : "memory");                             \
    if (!_d) {                                                                 \
        asm volatile(                                                          \
            "{\n\t.reg .pred P1;\n\t"                                          \
            "WL_%=:\n\t"                                                       \
            "mbarrier.try_wait.parity.acquire.cta.shared::cta.b64 P1, [%0], %1, 0x989680;\n\t" \
            "@P1 bra.uni WD_%=;\n\t"                                           \
            "bra.uni WL_%=;\n\t"                                               \
            "WD_%=:\n\t}"                                                      \
            :: "r"(_m), "r"(_p) : "memory");                                   \
    }                                                                          \
} while (0)

#define SW128(off) ((off) ^ (((off) >> 3) & 0x70))

// ---------------------------------------------------------------------------
// tcgen05-only helpers (expanded only inside the guarded body)
// ---------------------------------------------------------------------------
#define TCGEN05_ALLOC(res, n) \
    asm volatile("tcgen05.alloc.cta_group::1.sync.aligned.shared::cta.b32 [%0], %1;" \
                 :: "r"((uint32_t)(res)), "r"((uint32_t)(n)) : "memory")
#define TCGEN05_DEALLOC(tm, n) \
    asm volatile("tcgen05.dealloc.cta_group::1.sync.aligned.b32 %0, %1;" \
                 :: "r"(tm), "r"((uint32_t)(n)))
#define TCGEN05_RELINQ() \
    asm volatile("tcgen05.relinquish_alloc_permit.cta_group::1.sync.aligned;")
#define TCGEN05_COMMIT(mb) \
    asm volatile("tcgen05.commit.cta_group::1.mbarrier::arrive::one.shared::cluster.b64 [%0];" \
                 :: "r"((uint32_t)(mb)) : "memory")
#define TCGEN05_FENCE_AFTER() \
    asm volatile("tcgen05.fence::after_thread_sync;" ::: "memory")
#define TCGEN05_FENCE_BEFORE() \
    asm volatile("tcgen05.fence::before_thread_sync;" ::: "memory")
#define TCGEN05_WAIT_LD() \
    asm volatile("tcgen05.wait::ld.sync.aligned;" ::: "memory")
#define FENCE_ASYNC_SHARED() \
    asm volatile("fence.proxy.async.shared::cta;" ::: "memory")

#define TCGEN05_LD_X32(r, tm)                                                  \
    asm volatile(                                                              \
        "tcgen05.ld.sync.aligned.32x32b.x32.b32 "                              \
        "{%0, %1, %2, %3, %4, %5, %6, %7, "                                    \
        " %8, %9, %10, %11, %12, %13, %14, %15, "                              \
        " %16, %17, %18, %19, %20, %21, %22, %23, "                            \
        " %24, %25, %26, %27, %28, %29, %30, %31}, [%32];"                     \
        : "=r"((r)[0]),  "=r"((r)[1]),  "=r"((r)[2]),  "=r"((r)[3]),           \
          "=r"((r)[4]),  "=r"((r)[5]),  "=r"((r)[6]),  "=r"((r)[7]),           \
          "=r"((r)[8]),  "=r"((r)[9]),  "=r"((r)[10]), "=r"((r)[11]),          \
          "=r"((r)[12]), "=r"((r)[13]), "=r"((r)[14]), "=r"((r)[15]),          \
          "=r"((r)[16]), "=r"((r)[17]), "=r"((r)[18]), "=r"((r)[19]),          \
          "=r"((r)[20]), "=r"((r)[21]), "=r"((r)[22]), "=r"((r)[23]),          \
          "=r"((r)[24]), "=r"((r)[25]), "=r"((r)[26]), "=r"((r)[27]),          \
          "=r"((r)[28]), "=r"((r)[29]), "=r"((r)[30]), "=r"((r)[31])           \
        : "r"(tm))

#define TCGEN05_MMA_TF32_SS(d_tmem, a_desc, b_desc, idesc, enable)             \
    asm volatile(                                                              \
        "{\n\t.reg .pred p;\n\t"                                               \
        "setp.ne.u32 p, %4, 0;\n\t"                                            \
        "tcgen05.mma.cta_group::1.kind::tf32 [%0], %1, %2, %3, {%5, %5, %5, %5}, p;\n\t" \
        "}"                                                                    \
        :: "r"(d_tmem), "l"(a_desc), "l"(b_desc), "r"(idesc),                  \
           "r"((uint32_t)(enable)), "r"(0u)                                    \
        : "memory")

// SW128 descriptor: layout=2, version=1 (Blackwell), SBO=64, LBO=1 (128B rows)
static constexpr uint64_t SMEM_DESC_BASE_SW128 =
    (uint64_t(2) << 61) | (uint64_t(1) << 46) | (uint64_t(64) << 32) | (uint64_t(1) << 16);
#define MAKE_SMEM_DESC(a) (SMEM_DESC_BASE_SW128 | ((uint64_t)((a) >> 4) & 0x3FFF))

// idesc kind::tf32: dformat F32=1 [4:5], atype TF32=2 [7:9], btype TF32=2
// [10:12], N/8 [17:22] = 16 (N=128), M/16 [24:28] = 8 (M=128)
#define IDESC_TF32 ((1u << 4) | (2u << 7) | (2u << 10) | (16u << 17) | (8u << 24))

// ---------------------------------------------------------------------------
// K00: transpose Wp (d,c,hw) -> g_wpT[s][hw][c][d]  (+ tf32 pre-round)
// ---------------------------------------------------------------------------
__global__ void __launch_bounds__(256) transpose_wp_kernel(
    const float* __restrict__ wq, const float* __restrict__ wk, const float* __restrict__ wv)
{
    int idx = blockIdx.x * 256 + threadIdx.x;
    if (idx >= 3 * HW2 * 4096) return;
    int s = idx / (HW2 * 4096);
    int r = idx - s * (HW2 * 4096);
    int d  = r & 63;
    int c  = (r >> 6) & 63;
    int hw = r >> 12;
    const float* w = (s == 0) ? wq : (s == 1) ? wk : wv;
    g_wpT[idx] = f2tf(w[d * (64 * HW2) + c * HW2 + hw]);
}

// ---------------------------------------------------------------------------
// K0: WeffT precompute, stored [n_global][k_global] (K-major), tf32-rounded.
// Block per (m-tile 128 of k-rows, (s,hw,n)).
// ---------------------------------------------------------------------------
__global__ void __launch_bounds__(256) weff_kernel(const float* __restrict__ Wqkv)
{
    __shared__ float As[128][36];
    __shared__ float Bs[32][72];

    const int tid = threadIdx.x, warp = tid >> 5;
    const int y = blockIdx.y;
    const int s = y / (HW2 * NHEAD);
    const int rem = y - s * (HW2 * NHEAD);
    const int hw = rem / NHEAD;
    const int n  = rem - hw * NHEAD;
    const int m0 = blockIdx.x * 128;
    const int coloff = s * 768 + n * 64;
    const float* wpT = g_wpT + (size_t)(s * HW2 + hw) * 4096;
    const int wm = (warp >> 1) * 32;
    const int wn = (warp & 1) * 32;

    FragC acc[2][2];
#pragma unroll
    for (int i = 0; i < 2; i++)
#pragma unroll
        for (int j = 0; j < 2; j++) wmma::fill_fragment(acc[i][j], 0.f);

#pragma unroll
    for (int kt = 0; kt < 2; kt++) {
#pragma unroll
        for (int it = 0; it < 4; it++) {
            int idx = tid + it * 256;
            int r = idx >> 3, q = (idx & 7) << 2;
            float4 v = *reinterpret_cast<const float4*>(
                Wqkv + (size_t)(m0 + r) * D3 + coloff + kt * 32 + q);
            *reinterpret_cast<float4*>(&As[r][q]) = cvt4(v);
        }
#pragma unroll
        for (int it = 0; it < 2; it++) {
            int idx = tid + it * 256;
            int rr = idx >> 4, dd = (idx & 15) << 2;
            *reinterpret_cast<float4*>(&Bs[rr][dd]) =
                *reinterpret_cast<const float4*>(wpT + (kt * 32 + rr) * 64 + dd);
        }
        __syncthreads();

#pragma unroll
        for (int kk = 0; kk < 4; kk++) {
            FragA af[2];
            FragB bf[2];
#pragma unroll
            for (int i = 0; i < 2; i++)
                wmma::load_matrix_sync(af[i], &As[wm + i * 16][kk * 8], 36);
#pragma unroll
            for (int j = 0; j < 2; j++)
                wmma::load_matrix_sync(bf[j], &Bs[kk * 8][wn + j * 16], 72);
#pragma unroll
            for (int i = 0; i < 2; i++)
#pragma unroll
                for (int j = 0; j < 2; j++)
                    wmma::mma_sync(acc[i][j], af[i], bf[j], acc[i][j]);
        }
        __syncthreads();
    }

    // tf32-round the results, then transposed store -> g_weffT[n][k]
#pragma unroll
    for (int i = 0; i < 2; i++)
#pragma unroll
        for (int j = 0; j < 2; j++) {
#pragma unroll
            for (int e = 0; e < acc[i][j].num_elements; e++)
                acc[i][j].x[e] = f2tf(acc[i][j].x[e]);
            float* dst = g_weffT +
                (size_t)(coloff + wn + j * 16) * KBIG + (hw * 768 + m0 + wm + i * 16);
            wmma::store_matrix_sync(dst, acc[i][j], KBIG, wmma::mem_col_major);
        }
}

// ---------------------------------------------------------------------------
// K1: fused GEMM (1024 x 2304 x 37632) + bias + LayerNorm epilogue.
// grid (18, 8) = 144 CTAs, 256 threads.
// ---------------------------------------------------------------------------
#define OFF_A0   0
#define OFF_B0   32768
#define OFF_TM   65536
#define OFF_MB   65552
#define K1_SMEM_BYTES 67584   // max(tcgen05: 66560, fallback: 128*132*4)

__global__ void __launch_bounds__(256, 1) qkv_pool_ln_tc(
    const float* __restrict__ x,
    const float* __restrict__ bq, const float* __restrict__ bk, const float* __restrict__ bv,
    const float* __restrict__ gq, const float* __restrict__ gk, const float* __restrict__ gv,
    const float* __restrict__ eq, const float* __restrict__ ek, const float* __restrict__ ev)
{
#if HAS_TCGEN05
    // =======================================================================
    // tcgen05 tf32 SS body
    // =======================================================================
    extern __shared__ char smem[];
    const uint32_t sb = smem_to_u32(smem);
    const int tid = threadIdx.x, warp = tid >> 5, lane = tid & 31;
    const int m0 = blockIdx.y * 128, n0 = blockIdx.x * 128;

    if (warp == 0) TCGEN05_ALLOC(sb + OFF_TM, 128);
    if (tid == 0) {
        MBARRIER_INIT(sb + OFF_MB, 1);
        MBARRIER_INIT(sb + OFF_MB + 8, 1);
    }
    __syncthreads();
    uint32_t tmem;
    asm volatile("ld.shared.b32 %0, [%1];" : "=r"(tmem) : "r"(sb + OFF_TM));

    const int rA  = tid >> 3;              // base row, +32 per it
    const int q16 = (tid & 7) << 4;        // byte offset within 128B row
    uint32_t swoff[4];
#pragma unroll
    for (int it = 0; it < 4; it++)
        swoff[it] = SW128((uint32_t)((it * 32 + rA) * 128 + q16));

    const float* Ap = x       + (size_t)(m0 + rA) * KBIG + (q16 >> 2);
    const float* Bp = g_weffT + (size_t)(n0 + rA) * KBIG + (q16 >> 2);

    int ph[2] = {0, 0};

#pragma unroll 1
    for (int i = 0; i < KTILES; i++) {
        const int b = i & 1;
        if (i >= 2) {
            MBARRIER_WAIT_PARITY(sb + OFF_MB + b * 8, ph[b]);
            ph[b] ^= 1;
        }
        const uint32_t abase = sb + OFF_A0 + b * 16384;
        const uint32_t bbase = sb + OFF_B0 + b * 16384;
        const int k0 = i * 32;
#pragma unroll
        for (int it = 0; it < 4; it++) {
            float4 va = *reinterpret_cast<const float4*>(Ap + (size_t)(it * 32) * KBIG + k0);
            float4 vb = *reinterpret_cast<const float4*>(Bp + (size_t)(it * 32) * KBIG + k0);
            *reinterpret_cast<float4*>(smem + (OFF_A0 + b * 16384) + swoff[it]) = cvt4(va);
            *reinterpret_cast<float4*>(smem + (OFF_B0 + b * 16384) + swoff[it]) = cvt4(vb);
        }
        FENCE_ASYNC_SHARED();
        __syncthreads();

        if (warp == 0 && elect_one_pred()) {
            const uint64_t ad = MAKE_SMEM_DESC(abase);
            const uint64_t bd = MAKE_SMEM_DESC(bbase);
#pragma unroll
            for (int kk = 0; kk < 4; kk++)
                TCGEN05_MMA_TF32_SS(tmem, ad + kk * 2, bd + kk * 2, IDESC_TF32,
                                    (i > 0) || (kk > 0));
            TCGEN05_COMMIT(sb + OFF_MB + b * 8);
        }
    }

    MBARRIER_WAIT_PARITY(sb + OFF_MB,     ph[0]);
    MBARRIER_WAIT_PARITY(sb + OFF_MB + 8, ph[1]);
    TCGEN05_FENCE_AFTER();
    __syncthreads();

    if (warp < 4) {
        float dreg[128];
        uint32_t* du = reinterpret_cast<uint32_t*>(dreg);
#pragma unroll
        for (int base = 0; base < 128; base += 32) TCGEN05_LD_X32(du + base, tmem + base);
        TCGEN05_WAIT_LD();
        TCGEN05_FENCE_BEFORE();

        const int row = warp * 32 + lane;
        const int bt = m0 + row;
        const int bb = bt >> 6, t = bt & 63;
        const int s  = n0 / 768;
        const int nh0 = (n0 - s * 768) >> 6;
        const float* bias = (s == 0) ? bq : (s == 1) ? bk : bv;
        const float* gam  = (s == 0) ? gq : (s == 1) ? gk : gv;
        const float* bet  = (s == 0) ? eq : (s == 1) ? ek : ev;
        float* outp       = (s == 0) ? g_qb : (s == 1) ? g_kb : g_vb;

#pragma unroll
        for (int hh = 0; hh < 2; hh++) {
            const int c0 = hh << 6;
            float mu = 0.f;
#pragma unroll
            for (int d = 0; d < 64; d++) mu += dreg[c0 + d] + __ldg(bias + d);
            mu *= (1.f / 64.f);
            float var = 0.f;
#pragma unroll
            for (int d = 0; d < 64; d++) {
                float v = dreg[c0 + d] + __ldg(bias + d) - mu;
                var += v * v;
            }
            var *= (1.f / 64.f);
            const float rs = rsqrtf(var + 1e-5f);
            const size_t obase = (((size_t)bb * NHEAD + nh0 + hh) * 64 + t) * 64;
#pragma unroll
            for (int d = 0; d < 64; d++) {
                float v = (dreg[c0 + d] + __ldg(bias + d) - mu) * rs;
                outp[obase + d] = v * __ldg(gam + d) + __ldg(bet + d);
            }
        }
    }
    __syncthreads();
    if (warp == 0) {
        TCGEN05_RELINQ();
        TCGEN05_DEALLOC(tmem, 128);
    }
#else
    // =======================================================================
    // wmma HMMA tf32 fallback body (round-5 structure, B from weffT[n][k])
    // =======================================================================
    extern __shared__ char smem_c[];
    float* smemf = reinterpret_cast<float*>(smem_c);
    float (*As)[36]  = reinterpret_cast<float(*)[36]>(smemf);           // [m][k]
    float (*Bs)[36]  = reinterpret_cast<float(*)[36]>(smemf + 4608);    // [n][k]
    float (*Cs)[132] = reinterpret_cast<float(*)[132]>(smemf);          // reused

    const int tid = threadIdx.x, warp = tid >> 5;
    const int m0 = blockIdx.y * 128, n0 = blockIdx.x * 128;
    const int wm = (warp >> 2) * 64, wn = (warp & 3) * 32;

    const int r0 = tid >> 3;              // + it*32
    const int q  = (tid & 7) << 2;

    const float* Ap = x       + (size_t)(m0 + r0) * KBIG + q;
    const float* Bp = g_weffT + (size_t)(n0 + r0) * KBIG + q;

    FragC acc[4][2];
#pragma unroll
    for (int i = 0; i < 4; i++)
#pragma unroll
        for (int j = 0; j < 2; j++) wmma::fill_fragment(acc[i][j], 0.f);

    float4 ra[4], rb[4];
#pragma unroll
    for (int it = 0; it < 4; it++) {
        ra[it] = *reinterpret_cast<const float4*>(Ap + (size_t)(it * 32) * KBIG);
        rb[it] = *reinterpret_cast<const float4*>(Bp + (size_t)(it * 32) * KBIG);
    }
#pragma unroll
    for (int it = 0; it < 4; it++) {
        *reinterpret_cast<float4*>(&As[r0 + it * 32][q]) = cvt4(ra[it]);
        *reinterpret_cast<float4*>(&Bs[r0 + it * 32][q]) = rb[it];  // pre-rounded
    }
    __syncthreads();

#pragma unroll 1
    for (int kt = 0; kt < KTILES; kt++) {
        if (kt + 1 < KTILES) {
#pragma unroll
            for (int it = 0; it < 4; it++) {
                ra[it] = *reinterpret_cast<const float4*>(
                    Ap + (size_t)(it * 32) * KBIG + (kt + 1) * 32);
                rb[it] = *reinterpret_cast<const float4*>(
                    Bp + (size_t)(it * 32) * KBIG + (kt + 1) * 32);
            }
        }
#pragma unroll
        for (int kk = 0; kk < 4; kk++) {
            FragA af[4];
            FragBc bf[2];
#pragma unroll
            for (int i = 0; i < 4; i++)
                wmma::load_matrix_sync(af[i], &As[wm + i * 16][kk * 8], 36);
#pragma unroll
            for (int j = 0; j < 2; j++)
                wmma::load_matrix_sync(bf[j], &Bs[wn + j * 16][kk * 8], 36);
#pragma unroll
            for (int i = 0; i < 4; i++)
#pragma unroll
                for (int j = 0; j < 2; j++)
                    wmma::mma_sync(acc[i][j], af[i], bf[j], acc[i][j]);
        }
        __syncthreads();
        if (kt + 1 < KTILES) {
#pragma unroll
            for (int it = 0; it < 4; it++) {
                *reinterpret_cast<float4*>(&As[r0 + it * 32][q]) = cvt4(ra[it]);
                *reinterpret_cast<float4*>(&Bs[r0 + it * 32][q]) = rb[it];
            }
            __syncthreads();
        }
    }

#pragma unroll
    for (int i = 0; i < 4; i++)
#pragma unroll
        for (int j = 0; j < 2; j++)
            wmma::store_matrix_sync(&Cs[wm + i * 16][wn + j * 16], acc[i][j],
                                    132, wmma::mem_row_major);
    __syncthreads();

    {
        const int r  = tid >> 1;
        const int hh = tid & 1;
        const int s  = n0 / 768;
        const int nh = ((n0 - s * 768) >> 6) + hh;
        const float* bias = (s == 0) ? bq : (s == 1) ? bk : bv;
        const float* gam  = (s == 0) ? gq : (s == 1) ? gk : gv;
        const float* bet  = (s == 0) ? eq : (s == 1) ? ek : ev;
        float* outp       = (s == 0) ? g_qb : (s == 1) ? g_kb : g_vb;
        const int c0 = hh << 6;

        float mu = 0.f;
#pragma unroll
        for (int d = 0; d < 64; d++) mu += Cs[r][c0 + d] + bias[d];
        mu *= (1.f / 64.f);
        float var = 0.f;
#pragma unroll
        for (int d = 0; d < 64; d++) {
            float v = Cs[r][c0 + d] + bias[d] - mu;
            var += v * v;
        }
        var *= (1.f / 64.f);
        const float rs = rsqrtf(var + 1e-5f);

        const int bt = m0 + r;
        const int b = bt >> 6, t = bt & 63;
        const size_t obase = (((size_t)b * NHEAD + nh) * 64 + t) * 64;
#pragma unroll
        for (int d = 0; d < 64; d++) {
            float v = (Cs[r][c0 + d] + bias[d] - mu) * rs;
            outp[obase + d] = v * gam[d] + bet[d];
        }
    }
#endif
}

// ---------------------------------------------------------------------------
// K3: fused attention per (b,n)
// ---------------------------------------------------------------------------
#define ATTN_SMEM_FLOATS (3 * 64 * 65 + 127 * 65 + 64 * 65)
#define ATTN_SMEM_BYTES  (ATTN_SMEM_FLOATS * 4)

__global__ void __launch_bounds__(256) attn_kernel(const float* __restrict__ rel)
{
    extern __shared__ float sm[];
    float (*qs)[65] = reinterpret_cast<float(*)[65]>(sm);
    float (*ks)[65] = reinterpret_cast<float(*)[65]>(sm + 4160);
    float (*vs)[65] = reinterpret_cast<float(*)[65]>(sm + 8320);
    float (*rt)[65] = reinterpret_cast<float(*)[65]>(sm + 12480);
    float (*ss)[65] = reinterpret_cast<float(*)[65]>(sm + 12480 + 127 * 65);

    const int bn = blockIdx.x;
    const int tid = threadIdx.x;
    const size_t base = (size_t)bn * 4096;

    for (int idx = tid; idx < 4096; idx += 256) {
        int t = idx >> 6, c = idx & 63;
        qs[t][c] = g_qb[base + idx];
        ks[t][c] = g_kb[base + idx];
        vs[t][c] = g_vb[base + idx];
    }
    for (int idx = tid; idx < 127 * 64; idx += 256)
        rt[idx >> 6][idx & 63] = rel[idx];
    __syncthreads();

    const int u = tid & 63, tq = tid >> 6;
#pragma unroll 1
    for (int p = 0; p < 16; p++) {
        int t = p * 4 + tq;
        const float* rrow = rt[t - u + 63];
        float a1 = 0.f, a2 = 0.f;
#pragma unroll
        for (int c = 0; c < 64; c++) {
            float qv = qs[t][c];
            a1 += qv * ks[u][c];
            a2 += qv * rrow[c];
        }
        ss[t][u] = 0.125f * a1 + a2;
    }
    __syncthreads();

    if (tid < 64) {
        const int t = tid;
        float mx = -1e30f;
#pragma unroll 1
        for (int uu = 0; uu < 64; uu++) mx = fmaxf(mx, ss[t][uu]);
        float sum = 0.f;
#pragma unroll 1
        for (int uu = 0; uu < 64; uu++) {
            float e = __expf(ss[t][uu] - mx);
            ss[t][uu] = e;
            sum += e;
        }
        float inv = 1.f / sum;
#pragma unroll 1
        for (int uu = 0; uu < 64; uu++) ss[t][uu] *= inv;
    }
    __syncthreads();

    const int b = bn / NHEAD, nh = bn - b * NHEAD;
#pragma unroll 1
    for (int p = 0; p < 16; p++) {
        int t = p * 4 + tq;
        float o = qs[t][u];
#pragma unroll
        for (int uu = 0; uu < 64; uu++) o += ss[t][uu] * vs[uu][u];
        g_att[(size_t)(b * 64 + t) * 768 + nh * 64 + u] = o;
    }
}

// ---------------------------------------------------------------------------
// K4: output projection (1024 x 768 x 768) + bias (wmma; tiny)
// ---------------------------------------------------------------------------
#define PROJ_SMEM_BYTES (128 * 132 * 4)

__global__ void __launch_bounds__(256) proj_kernel(
    const float* __restrict__ B, const float* __restrict__ bias, float* __restrict__ C)
{
    extern __shared__ float smemf[];
    float (*As)[36]  = reinterpret_cast<float(*)[36]>(smemf);
    float (*Bs)[136] = reinterpret_cast<float(*)[136]>(smemf + 4608);
    float (*Cs)[132] = reinterpret_cast<float(*)[132]>(smemf);

    const int tid = threadIdx.x, warp = tid >> 5;
    const int m0 = blockIdx.y * 128, n0 = blockIdx.x * 128;
    const int wm = (warp >> 2) * 64, wn = (warp & 3) * 32;

    FragC acc[4][2];
#pragma unroll
    for (int i = 0; i < 4; i++)
#pragma unroll
        for (int j = 0; j < 2; j++) wmma::fill_fragment(acc[i][j], 0.f);

#pragma unroll 1
    for (int kt = 0; kt < 24; kt++) {
#pragma unroll
        for (int it = 0; it < 4; it++) {
            int idx = tid + it * 256;
            int r = idx >> 3, qq = (idx & 7) << 2;
            float4 v = *reinterpret_cast<const float4*>(
                g_att + (size_t)(m0 + r) * 768 + kt * 32 + qq);
            *reinterpret_cast<float4*>(&As[r][qq]) = cvt4(v);
        }
#pragma unroll
        for (int it = 0; it < 4; it++) {
            int idx = tid + it * 256;
            int r = idx >> 5, qq = (idx & 31) << 2;
            float4 v = *reinterpret_cast<const float4*>(
                B + (size_t)(kt * 32 + r) * 768 + n0 + qq);
            *reinterpret_cast<float4*>(&Bs[r][qq]) = cvt4(v);
        }
        __syncthreads();

#pragma unroll
        for (int kk = 0; kk < 4; kk++) {
            FragA af[4];
            FragB bf[2];
#pragma unroll
            for (int i = 0; i < 4; i++)
                wmma::load_matrix_sync(af[i], &As[wm + i * 16][kk * 8], 36);
#pragma unroll
            for (int j = 0; j < 2; j++)
                wmma::load_matrix_sync(bf[j], &Bs[kk * 8][wn + j * 16], 136);
#pragma unroll
            for (int i = 0; i < 4; i++)
#pragma unroll
                for (int j = 0; j < 2; j++)
                    wmma::mma_sync(acc[i][j], af[i], bf[j], acc[i][j]);
        }
        __syncthreads();
    }

#pragma unroll
    for (int i = 0; i < 4; i++)
#pragma unroll
        for (int j = 0; j < 2; j++)
            wmma::store_matrix_sync(&Cs[wm + i * 16][wn + j * 16], acc[i][j],
                                    132, wmma::mem_row_major);
    __syncthreads();

    {
        const int r = tid >> 1;
        const int c0 = (tid & 1) << 6;
#pragma unroll
        for (int d = 0; d < 64; d++) {
            int col = c0 + d;
            C[(size_t)(m0 + r) * 768 + n0 + col] = Cs[r][col] + bias[n0 + col];
        }
    }
}

// ---------------------------------------------------------------------------
// Orchestration
// ---------------------------------------------------------------------------
extern "C" void kernel_launch(void* const* d_in, const int* in_sizes, int n_in,
                              void* d_out, int out_size)
{
    const float* x      = (const float*)d_in[0];
    const float* W_qkv  = (const float*)d_in[1];
    const float* Wpq    = (const float*)d_in[2];
    const float* bpq    = (const float*)d_in[3];
    const float* Wpk    = (const float*)d_in[4];
    const float* bpk    = (const float*)d_in[5];
    const float* Wpv    = (const float*)d_in[6];
    const float* bpv    = (const float*)d_in[7];
    const float* g_q    = (const float*)d_in[8];
    const float* be_q   = (const float*)d_in[9];
    const float* g_k    = (const float*)d_in[10];
    const float* be_k   = (const float*)d_in[11];
    const float* g_v    = (const float*)d_in[12];
    const float* be_v   = (const float*)d_in[13];
    const float* rel    = (const float*)d_in[14];
    const float* W_proj = (const float*)d_in[15];
    const float* b_proj = (const float*)d_in[16];
    float* out = (float*)d_out;

    cudaFuncSetAttribute(qkv_pool_ln_tc,
                         cudaFuncAttributeMaxDynamicSharedMemorySize, K1_SMEM_BYTES);
    cudaFuncSetAttribute(proj_kernel,
                         cudaFuncAttributeMaxDynamicSharedMemorySize, PROJ_SMEM_BYTES);
    cudaFuncSetAttribute(attn_kernel,
                         cudaFuncAttributeMaxDynamicSharedMemorySize, ATTN_SMEM_BYTES);

    // K00: tiny Wp transpose (+ tf32 pre-round)
    transpose_wp_kernel<<<(3 * HW2 * 4096 + 255) / 256, 256>>>(Wpq, Wpk, Wpv);

    // K0: WeffT precompute (K-major store, tf32-rounded)
    weff_kernel<<<dim3(6, 3 * HW2 * NHEAD), 256>>>(W_qkv);

    // K1: fused qkv+pool GEMM + bias + LayerNorm (tcgen05 or wmma per pass)
    qkv_pool_ln_tc<<<dim3(D3 / 128, BT / 128), 256, K1_SMEM_BYTES>>>(
        x, bpq, bpk, bpv, g_q, g_k, g_v, be_q, be_k, be_v);

    // K3: attention per (b,n)
    attn_kernel<<<16 * NHEAD, 256, ATTN_SMEM_BYTES>>>(rel);

    // K4: output projection + bias
    proj_kernel<<<dim3(768 / 128, BT / 128), 256, PROJ_SMEM_BYTES>>>(
        W_proj, b_proj, out);
}

// round 12
// speedup vs baseline: 2.7804x; 1.5001x over previous
#include <cuda_runtime.h>
#include <mma.h>
#include <cstdint>
#include <cstddef>

using namespace nvcuda;

// ---------------------------------------------------------------------------
// B=16, T=64, HW=7 (49), D=768, N=12 heads, C=64, EPS=1e-5
//   WeffT[s*768+n*64+d, hw*768+k] = sum_c W_qkv[k, s*768+n*64+c]*Wp_s[d,c,hw]
//   qkv_pooled[bt, nd] = sum_kk x[bt, kk] * WeffT[nd, kk]
// -> ONE GEMM (1024 x 2304 x 37632), epilogue bias+LayerNorm.
// K1 bodies per gencode pass:
//   - tcgen05 tf32 SS, 4-stage smem ring + ping-pong register prefetch
//   - wmma HMMA tf32 fallback
// NOTE: smem size must be the HOST-side max of both bodies (the arch-feature
// macros are undefined on the host pass — round-9 crash root cause).
// ---------------------------------------------------------------------------
#define BT     1024
#define D3     2304
#define KBIG   37632        // 49*768
#define NHEAD  12
#define HW2    49
#define KTILES (KBIG / 32)  // 1176 (divisible by 4)

#if defined(__CUDA_ARCH_FEAT_SM103_ALL) || defined(__CUDA_ARCH_FEAT_SM100_ALL) || defined(__CUDA_ARCH_FEAT_SM101_ALL)
#define HAS_TCGEN05 1
#else
#define HAS_TCGEN05 0
#endif

// ---------------------------------------------------------------------------
// Device scratch (statics; no runtime allocation)
// ---------------------------------------------------------------------------
__device__ float g_weffT[(size_t)D3 * KBIG];   // [n_global][k_global], 346.8 MB
__device__ float g_wpT[3 * HW2 * 64 * 64];     // Wp transposed [s][hw][c][d]
__device__ float g_qb[BT * 768];               // (B,N,T,C) post-LN q
__device__ float g_kb[BT * 768];
__device__ float g_vb[BT * 768];
__device__ float g_att[BT * 768];              // (B,T,768) attention out

// ---------------------------------------------------------------------------
// Common helpers
// ---------------------------------------------------------------------------
__device__ __forceinline__ float f2tf(float x) {
    uint32_t u;
    asm("cvt.rna.tf32.f32 %0, %1;" : "=r"(u) : "f"(x));
    return __uint_as_float(u);
}
__device__ __forceinline__ float4 cvt4(float4 v) {
    float4 w;
    w.x = f2tf(v.x); w.y = f2tf(v.y); w.z = f2tf(v.z); w.w = f2tf(v.w);
    return w;
}

typedef wmma::fragment<wmma::matrix_a, 16, 16, 8, wmma::precision::tf32, wmma::row_major> FragA;
typedef wmma::fragment<wmma::matrix_b, 16, 16, 8, wmma::precision::tf32, wmma::row_major> FragB;
typedef wmma::fragment<wmma::matrix_b, 16, 16, 8, wmma::precision::tf32, wmma::col_major> FragBc;
typedef wmma::fragment<wmma::accumulator, 16, 16, 8, float> FragC;

__device__ __forceinline__ uint32_t elect_one_pred() {
    uint32_t pred;
    asm volatile(
        "{\n\t.reg .pred p;\n\t"
        "elect.sync _|p, 0xFFFFFFFF;\n\t"
        "selp.b32 %0, 1, 0, p;\n\t}"
        : "=r"(pred));
    return pred;
}
__device__ __forceinline__ uint32_t smem_to_u32(const void* p) {
    uint32_t a;
    asm("{ .reg .u64 t; cvta.to.shared.u64 t, %1; cvt.u32.u64 %0, t; }"
        : "=r"(a) : "l"(p));
    return a;
}

#define MBARRIER_INIT(addr, cnt) \
    asm volatile("mbarrier.init.shared.b64 [%0], %1;" :: "r"(addr), "r"(cnt) : "memory")

#define MBARRIER_WAIT_PARITY(addr, par) do {                                   \
    uint32_t _m = (addr), _p = (par), _d;                                      \
    asm volatile(                                                              \
        "{\n\t.reg .pred p;\n\t"                                               \
        "mbarrier.try_wait.parity.acquire.cta.shared::cta.b64 p, [%1], %2;\n\t"\
        "selp.b32 %0, 1, 0, p;\n\t}"                                           \
        : "=r"(_d) : "r"(_m), "r"(_p) : "memory");                             \
    if (!_d) {                                                                 \
        asm volatile(                                                          \
            "{\n\t.reg .pred P1;\n\t"                                          \
            "WL_%=:\n\t"                                                       \
            "mbarrier.try_wait.parity.acquire.cta.shared::cta.b64 P1, [%0], %1, 0x989680;\n\t" \
            "@P1 bra.uni WD_%=;\n\t"                                           \
            "bra.uni WL_%=;\n\t"                                               \
            "WD_%=:\n\t}"                                                      \
            :: "r"(_m), "r"(_p) : "memory");                                   \
    }                                                                          \
} while (0)

#define SW128(off) ((off) ^ (((off) >> 3) & 0x70))

// ---------------------------------------------------------------------------
// tcgen05-only helpers (expanded only inside the guarded body)
// ---------------------------------------------------------------------------
#define TCGEN05_ALLOC(res, n) \
    asm volatile("tcgen05.alloc.cta_group::1.sync.aligned.shared::cta.b32 [%0], %1;" \
                 :: "r"((uint32_t)(res)), "r"((uint32_t)(n)) : "memory")
#define TCGEN05_DEALLOC(tm, n) \
    asm volatile("tcgen05.dealloc.cta_group::1.sync.aligned.b32 %0, %1;" \
                 :: "r"(tm), "r"((uint32_t)(n)))
#define TCGEN05_RELINQ() \
    asm volatile("tcgen05.relinquish_alloc_permit.cta_group::1.sync.aligned;")
#define TCGEN05_COMMIT(mb) \
    asm volatile("tcgen05.commit.cta_group::1.mbarrier::arrive::one.shared::cluster.b64 [%0];" \
                 :: "r"((uint32_t)(mb)) : "memory")
#define TCGEN05_FENCE_AFTER() \
    asm volatile("tcgen05.fence::after_thread_sync;" ::: "memory")
#define TCGEN05_FENCE_BEFORE() \
    asm volatile("tcgen05.fence::before_thread_sync;" ::: "memory")
#define TCGEN05_WAIT_LD() \
    asm volatile("tcgen05.wait::ld.sync.aligned;" ::: "memory")
#define FENCE_ASYNC_SHARED() \
    asm volatile("fence.proxy.async.shared::cta;" ::: "memory")

#define TCGEN05_LD_X32(r, tm)                                                  \
    asm volatile(                                                              \
        "tcgen05.ld.sync.aligned.32x32b.x32.b32 "                              \
        "{%0, %1, %2, %3, %4, %5, %6, %7, "                                    \
        " %8, %9, %10, %11, %12, %13, %14, %15, "                              \
        " %16, %17, %18, %19, %20, %21, %22, %23, "                            \
        " %24, %25, %26, %27, %28, %29, %30, %31}, [%32];"                     \
        : "=r"((r)[0]),  "=r"((r)[1]),  "=r"((r)[2]),  "=r"((r)[3]),           \
          "=r"((r)[4]),  "=r"((r)[5]),  "=r"((r)[6]),  "=r"((r)[7]),           \
          "=r"((r)[8]),  "=r"((r)[9]),  "=r"((r)[10]), "=r"((r)[11]),          \
          "=r"((r)[12]), "=r"((r)[13]), "=r"((r)[14]), "=r"((r)[15]),          \
          "=r"((r)[16]), "=r"((r)[17]), "=r"((r)[18]), "=r"((r)[19]),          \
          "=r"((r)[20]), "=r"((r)[21]), "=r"((r)[22]), "=r"((r)[23]),          \
          "=r"((r)[24]), "=r"((r)[25]), "=r"((r)[26]), "=r"((r)[27]),          \
          "=r"((r)[28]), "=r"((r)[29]), "=r"((r)[30]), "=r"((r)[31])           \
        : "r"(tm))

#define TCGEN05_MMA_TF32_SS(d_tmem, a_desc, b_desc, idesc, enable)             \
    asm volatile(                                                              \
        "{\n\t.reg .pred p;\n\t"                                               \
        "setp.ne.u32 p, %4, 0;\n\t"                                            \
        "tcgen05.mma.cta_group::1.kind::tf32 [%0], %1, %2, %3, {%5, %5, %5, %5}, p;\n\t" \
        "}"                                                                    \
        :: "r"(d_tmem), "l"(a_desc), "l"(b_desc), "r"(idesc),                  \
           "r"((uint32_t)(enable)), "r"(0u)                                    \
        : "memory")

// SW128 descriptor: layout=2, version=1 (Blackwell), SBO=64, LBO=1 (128B rows)
static constexpr uint64_t SMEM_DESC_BASE_SW128 =
    (uint64_t(2) << 61) | (uint64_t(1) << 46) | (uint64_t(64) << 32) | (uint64_t(1) << 16);
#define MAKE_SMEM_DESC(a) (SMEM_DESC_BASE_SW128 | ((uint64_t)((a) >> 4) & 0x3FFF))

// idesc kind::tf32: dformat F32=1 [4:5], atype TF32=2 [7:9], btype TF32=2
// [10:12], N/8 [17:22] = 16 (N=128), M/16 [24:28] = 8 (M=128)
#define IDESC_TF32 ((1u << 4) | (2u << 7) | (2u << 10) | (16u << 17) | (8u << 24))

// ---------------------------------------------------------------------------
// K00: transpose Wp (d,c,hw) -> g_wpT[s][hw][c][d]  (+ tf32 pre-round)
// ---------------------------------------------------------------------------
__global__ void __launch_bounds__(256) transpose_wp_kernel(
    const float* __restrict__ wq, const float* __restrict__ wk, const float* __restrict__ wv)
{
    int idx = blockIdx.x * 256 + threadIdx.x;
    if (idx >= 3 * HW2 * 4096) return;
    int s = idx / (HW2 * 4096);
    int r = idx - s * (HW2 * 4096);
    int d  = r & 63;
    int c  = (r >> 6) & 63;
    int hw = r >> 12;
    const float* w = (s == 0) ? wq : (s == 1) ? wk : wv;
    g_wpT[idx] = f2tf(w[d * (64 * HW2) + c * HW2 + hw]);
}

// ---------------------------------------------------------------------------
// K0: WeffT precompute, stored [n_global][k_global] (K-major), tf32-rounded.
// ---------------------------------------------------------------------------
__global__ void __launch_bounds__(256) weff_kernel(const float* __restrict__ Wqkv)
{
    __shared__ float As[128][36];
    __shared__ float Bs[32][72];

    const int tid = threadIdx.x, warp = tid >> 5;
    const int y = blockIdx.y;
    const int s = y / (HW2 * NHEAD);
    const int rem = y - s * (HW2 * NHEAD);
    const int hw = rem / NHEAD;
    const int n  = rem - hw * NHEAD;
    const int m0 = blockIdx.x * 128;
    const int coloff = s * 768 + n * 64;
    const float* wpT = g_wpT + (size_t)(s * HW2 + hw) * 4096;
    const int wm = (warp >> 1) * 32;
    const int wn = (warp & 1) * 32;

    FragC acc[2][2];
#pragma unroll
    for (int i = 0; i < 2; i++)
#pragma unroll
        for (int j = 0; j < 2; j++) wmma::fill_fragment(acc[i][j], 0.f);

#pragma unroll
    for (int kt = 0; kt < 2; kt++) {
#pragma unroll
        for (int it = 0; it < 4; it++) {
            int idx = tid + it * 256;
            int r = idx >> 3, q = (idx & 7) << 2;
            float4 v = *reinterpret_cast<const float4*>(
                Wqkv + (size_t)(m0 + r) * D3 + coloff + kt * 32 + q);
            *reinterpret_cast<float4*>(&As[r][q]) = cvt4(v);
        }
#pragma unroll
        for (int it = 0; it < 2; it++) {
            int idx = tid + it * 256;
            int rr = idx >> 4, dd = (idx & 15) << 2;
            *reinterpret_cast<float4*>(&Bs[rr][dd]) =
                *reinterpret_cast<const float4*>(wpT + (kt * 32 + rr) * 64 + dd);
        }
        __syncthreads();

#pragma unroll
        for (int kk = 0; kk < 4; kk++) {
            FragA af[2];
            FragB bf[2];
#pragma unroll
            for (int i = 0; i < 2; i++)
                wmma::load_matrix_sync(af[i], &As[wm + i * 16][kk * 8], 36);
#pragma unroll
            for (int j = 0; j < 2; j++)
                wmma::load_matrix_sync(bf[j], &Bs[kk * 8][wn + j * 16], 72);
#pragma unroll
            for (int i = 0; i < 2; i++)
#pragma unroll
                for (int j = 0; j < 2; j++)
                    wmma::mma_sync(acc[i][j], af[i], bf[j], acc[i][j]);
        }
        __syncthreads();
    }

#pragma unroll
    for (int i = 0; i < 2; i++)
#pragma unroll
        for (int j = 0; j < 2; j++) {
#pragma unroll
            for (int e = 0; e < acc[i][j].num_elements; e++)
                acc[i][j].x[e] = f2tf(acc[i][j].x[e]);
            float* dst = g_weffT +
                (size_t)(coloff + wn + j * 16) * KBIG + (hw * 768 + m0 + wm + i * 16);
            wmma::store_matrix_sync(dst, acc[i][j], KBIG, wmma::mem_col_major);
        }
}

// ---------------------------------------------------------------------------
// K1: fused GEMM (1024 x 2304 x 37632) + bias + LayerNorm epilogue.
// grid (18, 8) = 144 CTAs, 256 threads.
// tcgen05 body: 4-stage smem ring, ping-pong register prefetch.
// K1_SMEM_BYTES is the max over BOTH bodies and is used identically on host
// and device (fix for round-9 OOB: host pass lacks the feature macros).
// ---------------------------------------------------------------------------
#define ST_A(s)  ((s) * 16384)
#define ST_B(s)  (65536 + (s) * 16384)
#define OFF_TM   131072
#define OFF_MB   131080
#define K1_SMEM_BYTES 131200

__global__ void __launch_bounds__(256, 1) qkv_pool_ln_tc(
    const float* __restrict__ x,
    const float* __restrict__ bq, const float* __restrict__ bk, const float* __restrict__ bv,
    const float* __restrict__ gq, const float* __restrict__ gk, const float* __restrict__ gv,
    const float* __restrict__ eq, const float* __restrict__ ek, const float* __restrict__ ev)
{
#if HAS_TCGEN05
    // =======================================================================
    // tcgen05 tf32 SS body — 4-stage pipeline + register prefetch
    // =======================================================================
    extern __shared__ char smem[];
    const uint32_t sb = smem_to_u32(smem);
    const int tid = threadIdx.x, warp = tid >> 5, lane = tid & 31;
    const int m0 = blockIdx.y * 128, n0 = blockIdx.x * 128;

    if (warp == 0) TCGEN05_ALLOC(sb + OFF_TM, 128);
    if (tid == 0) {
#pragma unroll
        for (int s = 0; s < 4; s++) MBARRIER_INIT(sb + OFF_MB + s * 8, 1);
    }
    __syncthreads();
    uint32_t tmem;
    asm volatile("ld.shared.b32 %0, [%1];" : "=r"(tmem) : "r"(sb + OFF_TM));

    const int rA  = tid >> 3;              // base row, +32 per it
    const int q16 = (tid & 7) << 4;        // byte offset within 128B row
    uint32_t swoff[4];
#pragma unroll
    for (int it = 0; it < 4; it++)
        swoff[it] = SW128((uint32_t)((it * 32 + rA) * 128 + q16));

    const float* Ap = x       + (size_t)(m0 + rA) * KBIG + (q16 >> 2);
    const float* Bp = g_weffT + (size_t)(n0 + rA) * KBIG + (q16 >> 2);

    float4 ra[2][4], rb[2][4];
#pragma unroll
    for (int it = 0; it < 4; it++) {
        ra[0][it] = *reinterpret_cast<const float4*>(Ap + (size_t)(it * 32) * KBIG);
        rb[0][it] = *reinterpret_cast<const float4*>(Bp + (size_t)(it * 32) * KBIG);
    }

    int ph[4] = {0, 0, 0, 0};

#pragma unroll 1
    for (int ii = 0; ii < KTILES; ii += 4) {
#pragma unroll
        for (int u = 0; u < 4; u++) {
            const int i = ii + u;
            const int cur = u & 1;
            const int nxt = cur ^ 1;
            // prefetch tile i+1 into the other register set (overlaps wait+MMA)
            if (i + 1 < KTILES) {
                const int k1 = (i + 1) * 32;
#pragma unroll
                for (int it = 0; it < 4; it++) {
                    ra[nxt][it] = *reinterpret_cast<const float4*>(
                        Ap + (size_t)(it * 32) * KBIG + k1);
                    rb[nxt][it] = *reinterpret_cast<const float4*>(
                        Bp + (size_t)(it * 32) * KBIG + k1);
                }
            }
            // recycle stage u (wait for MMA from iter i-4)
            if (ii >= 4) {
                MBARRIER_WAIT_PARITY(sb + OFF_MB + u * 8, ph[u]);
                ph[u] ^= 1;
            }
            // store current tile into stage u
#pragma unroll
            for (int it = 0; it < 4; it++) {
                *reinterpret_cast<float4*>(smem + ST_A(u) + swoff[it]) = cvt4(ra[cur][it]);
                *reinterpret_cast<float4*>(smem + ST_B(u) + swoff[it]) = rb[cur][it];
            }
            FENCE_ASYNC_SHARED();
            __syncthreads();

            if (warp == 0 && elect_one_pred()) {
                const uint64_t ad = MAKE_SMEM_DESC(sb + ST_A(u));
                const uint64_t bd = MAKE_SMEM_DESC(sb + ST_B(u));
#pragma unroll
                for (int kk = 0; kk < 4; kk++)
                    TCGEN05_MMA_TF32_SS(tmem, ad + kk * 2, bd + kk * 2, IDESC_TF32,
                                        (i > 0) || (kk > 0));
                TCGEN05_COMMIT(sb + OFF_MB + u * 8);
            }
        }
    }

#pragma unroll
    for (int s = 0; s < 4; s++) MBARRIER_WAIT_PARITY(sb + OFF_MB + s * 8, ph[s]);
    TCGEN05_FENCE_AFTER();
    __syncthreads();

    if (warp < 4) {
        float dreg[128];
        uint32_t* du = reinterpret_cast<uint32_t*>(dreg);
#pragma unroll
        for (int base = 0; base < 128; base += 32) TCGEN05_LD_X32(du + base, tmem + base);
        TCGEN05_WAIT_LD();
        TCGEN05_FENCE_BEFORE();

        const int row = warp * 32 + lane;
        const int bt = m0 + row;
        const int bb = bt >> 6, t = bt & 63;
        const int s  = n0 / 768;
        const int nh0 = (n0 - s * 768) >> 6;
        const float* bias = (s == 0) ? bq : (s == 1) ? bk : bv;
        const float* gam  = (s == 0) ? gq : (s == 1) ? gk : gv;
        const float* bet  = (s == 0) ? eq : (s == 1) ? ek : ev;
        float* outp       = (s == 0) ? g_qb : (s == 1) ? g_kb : g_vb;

#pragma unroll
        for (int hh = 0; hh < 2; hh++) {
            const int c0 = hh << 6;
            float mu = 0.f;
#pragma unroll
            for (int d = 0; d < 64; d++) mu += dreg[c0 + d] + __ldg(bias + d);
            mu *= (1.f / 64.f);
            float var = 0.f;
#pragma unroll
            for (int d = 0; d < 64; d++) {
                float v = dreg[c0 + d] + __ldg(bias + d) - mu;
                var += v * v;
            }
            var *= (1.f / 64.f);
            const float rs = rsqrtf(var + 1e-5f);
            const size_t obase = (((size_t)bb * NHEAD + nh0 + hh) * 64 + t) * 64;
#pragma unroll
            for (int d = 0; d < 64; d++) {
                float v = (dreg[c0 + d] + __ldg(bias + d) - mu) * rs;
                outp[obase + d] = v * __ldg(gam + d) + __ldg(bet + d);
            }
        }
    }
    __syncthreads();
    if (warp == 0) {
        TCGEN05_RELINQ();
        TCGEN05_DEALLOC(tmem, 128);
    }
#else
    // =======================================================================
    // wmma HMMA tf32 fallback body
    // =======================================================================
    extern __shared__ char smem_c[];
    float* smemf = reinterpret_cast<float*>(smem_c);
    float (*As)[36]  = reinterpret_cast<float(*)[36]>(smemf);           // [m][k]
    float (*Bs)[36]  = reinterpret_cast<float(*)[36]>(smemf + 4608);    // [n][k]
    float (*Cs)[132] = reinterpret_cast<float(*)[132]>(smemf);          // reused

    const int tid = threadIdx.x, warp = tid >> 5;
    const int m0 = blockIdx.y * 128, n0 = blockIdx.x * 128;
    const int wm = (warp >> 2) * 64, wn = (warp & 3) * 32;

    const int r0 = tid >> 3;              // + it*32
    const int q  = (tid & 7) << 2;

    const float* Ap = x       + (size_t)(m0 + r0) * KBIG + q;
    const float* Bp = g_weffT + (size_t)(n0 + r0) * KBIG + q;

    FragC acc[4][2];
#pragma unroll
    for (int i = 0; i < 4; i++)
#pragma unroll
        for (int j = 0; j < 2; j++) wmma::fill_fragment(acc[i][j], 0.f);

    float4 ra[4], rb[4];
#pragma unroll
    for (int it = 0; it < 4; it++) {
        ra[it] = *reinterpret_cast<const float4*>(Ap + (size_t)(it * 32) * KBIG);
        rb[it] = *reinterpret_cast<const float4*>(Bp + (size_t)(it * 32) * KBIG);
    }
#pragma unroll
    for (int it = 0; it < 4; it++) {
        *reinterpret_cast<float4*>(&As[r0 + it * 32][q]) = cvt4(ra[it]);
        *reinterpret_cast<float4*>(&Bs[r0 + it * 32][q]) = rb[it];  // pre-rounded
    }
    __syncthreads();

#pragma unroll 1
    for (int kt = 0; kt < KTILES; kt++) {
        if (kt + 1 < KTILES) {
#pragma unroll
            for (int it = 0; it < 4; it++) {
                ra[it] = *reinterpret_cast<const float4*>(
                    Ap + (size_t)(it * 32) * KBIG + (kt + 1) * 32);
                rb[it] = *reinterpret_cast<const float4*>(
                    Bp + (size_t)(it * 32) * KBIG + (kt + 1) * 32);
            }
        }
#pragma unroll
        for (int kk = 0; kk < 4; kk++) {
            FragA af[4];
            FragBc bf[2];
#pragma unroll
            for (int i = 0; i < 4; i++)
                wmma::load_matrix_sync(af[i], &As[wm + i * 16][kk * 8], 36);
#pragma unroll
            for (int j = 0; j < 2; j++)
                wmma::load_matrix_sync(bf[j], &Bs[wn + j * 16][kk * 8], 36);
#pragma unroll
            for (int i = 0; i < 4; i++)
#pragma unroll
                for (int j = 0; j < 2; j++)
                    wmma::mma_sync(acc[i][j], af[i], bf[j], acc[i][j]);
        }
        __syncthreads();
        if (kt + 1 < KTILES) {
#pragma unroll
            for (int it = 0; it < 4; it++) {
                *reinterpret_cast<float4*>(&As[r0 + it * 32][q]) = cvt4(ra[it]);
                *reinterpret_cast<float4*>(&Bs[r0 + it * 32][q]) = rb[it];
            }
            __syncthreads();
        }
    }

#pragma unroll
    for (int i = 0; i < 4; i++)
#pragma unroll
        for (int j = 0; j < 2; j++)
            wmma::store_matrix_sync(&Cs[wm + i * 16][wn + j * 16], acc[i][j],
                                    132, wmma::mem_row_major);
    __syncthreads();

    {
        const int r  = tid >> 1;
        const int hh = tid & 1;
        const int s  = n0 / 768;
        const int nh = ((n0 - s * 768) >> 6) + hh;
        const float* bias = (s == 0) ? bq : (s == 1) ? bk : bv;
        const float* gam  = (s == 0) ? gq : (s == 1) ? gk : gv;
        const float* bet  = (s == 0) ? eq : (s == 1) ? ek : ev;
        float* outp       = (s == 0) ? g_qb : (s == 1) ? g_kb : g_vb;
        const int c0 = hh << 6;

        float mu = 0.f;
#pragma unroll
        for (int d = 0; d < 64; d++) mu += Cs[r][c0 + d] + bias[d];
        mu *= (1.f / 64.f);
        float var = 0.f;
#pragma unroll
        for (int d = 0; d < 64; d++) {
            float v = Cs[r][c0 + d] + bias[d] - mu;
            var += v * v;
        }
        var *= (1.f / 64.f);
        const float rs = rsqrtf(var + 1e-5f);

        const int bt = m0 + r;
        const int b = bt >> 6, t = bt & 63;
        const size_t obase = (((size_t)b * NHEAD + nh) * 64 + t) * 64;
#pragma unroll
        for (int d = 0; d < 64; d++) {
            float v = (Cs[r][c0 + d] + bias[d] - mu) * rs;
            outp[obase + d] = v * gam[d] + bet[d];
        }
    }
#endif
}

// ---------------------------------------------------------------------------
// K3: fused attention per (b,n)
// ---------------------------------------------------------------------------
#define ATTN_SMEM_FLOATS (3 * 64 * 65 + 127 * 65 + 64 * 65)
#define ATTN_SMEM_BYTES  (ATTN_SMEM_FLOATS * 4)

__global__ void __launch_bounds__(256) attn_kernel(const float* __restrict__ rel)
{
    extern __shared__ float sm[];
    float (*qs)[65] = reinterpret_cast<float(*)[65]>(sm);
    float (*ks)[65] = reinterpret_cast<float(*)[65]>(sm + 4160);
    float (*vs)[65] = reinterpret_cast<float(*)[65]>(sm + 8320);
    float (*rt)[65] = reinterpret_cast<float(*)[65]>(sm + 12480);
    float (*ss)[65] = reinterpret_cast<float(*)[65]>(sm + 12480 + 127 * 65);

    const int bn = blockIdx.x;
    const int tid = threadIdx.x;
    const size_t base = (size_t)bn * 4096;

    for (int idx = tid; idx < 4096; idx += 256) {
        int t = idx >> 6, c = idx & 63;
        qs[t][c] = g_qb[base + idx];
        ks[t][c] = g_kb[base + idx];
        vs[t][c] = g_vb[base + idx];
    }
    for (int idx = tid; idx < 127 * 64; idx += 256)
        rt[idx >> 6][idx & 63] = rel[idx];
    __syncthreads();

    const int u = tid & 63, tq = tid >> 6;
#pragma unroll 1
    for (int p = 0; p < 16; p++) {
        int t = p * 4 + tq;
        const float* rrow = rt[t - u + 63];
        float a1 = 0.f, a2 = 0.f;
#pragma unroll
        for (int c = 0; c < 64; c++) {
            float qv = qs[t][c];
            a1 += qv * ks[u][c];
            a2 += qv * rrow[c];
        }
        ss[t][u] = 0.125f * a1 + a2;
    }
    __syncthreads();

    if (tid < 64) {
        const int t = tid;
        float mx = -1e30f;
#pragma unroll 1
        for (int uu = 0; uu < 64; uu++) mx = fmaxf(mx, ss[t][uu]);
        float sum = 0.f;
#pragma unroll 1
        for (int uu = 0; uu < 64; uu++) {
            float e = __expf(ss[t][uu] - mx);
            ss[t][uu] = e;
            sum += e;
        }
        float inv = 1.f / sum;
#pragma unroll 1
        for (int uu = 0; uu < 64; uu++) ss[t][uu] *= inv;
    }
    __syncthreads();

    const int b = bn / NHEAD, nh = bn - b * NHEAD;
#pragma unroll 1
    for (int p = 0; p < 16; p++) {
        int t = p * 4 + tq;
        float o = qs[t][u];
#pragma unroll
        for (int uu = 0; uu < 64; uu++) o += ss[t][uu] * vs[uu][u];
        g_att[(size_t)(b * 64 + t) * 768 + nh * 64 + u] = o;
    }
}

// ---------------------------------------------------------------------------
// K4: output projection (1024 x 768 x 768) + bias (wmma; tiny)
// ---------------------------------------------------------------------------
#define PROJ_SMEM_BYTES (128 * 132 * 4)

__global__ void __launch_bounds__(256) proj_kernel(
    const float* __restrict__ B, const float* __restrict__ bias, float* __restrict__ C)
{
    extern __shared__ float smemf[];
    float (*As)[36]  = reinterpret_cast<float(*)[36]>(smemf);
    float (*Bs)[136] = reinterpret_cast<float(*)[136]>(smemf + 4608);
    float (*Cs)[132] = reinterpret_cast<float(*)[132]>(smemf);

    const int tid = threadIdx.x, warp = tid >> 5;
    const int m0 = blockIdx.y * 128, n0 = blockIdx.x * 128;
    const int wm = (warp >> 2) * 64, wn = (warp & 3) * 32;

    FragC acc[4][2];
#pragma unroll
    for (int i = 0; i < 4; i++)
#pragma unroll
        for (int j = 0; j < 2; j++) wmma::fill_fragment(acc[i][j], 0.f);

#pragma unroll 1
    for (int kt = 0; kt < 24; kt++) {
#pragma unroll
        for (int it = 0; it < 4; it++) {
            int idx = tid + it * 256;
            int r = idx >> 3, qq = (idx & 7) << 2;
            float4 v = *reinterpret_cast<const float4*>(
                g_att + (size_t)(m0 + r) * 768 + kt * 32 + qq);
            *reinterpret_cast<float4*>(&As[r][qq]) = cvt4(v);
        }
#pragma unroll
        for (int it = 0; it < 4; it++) {
            int idx = tid + it * 256;
            int r = idx >> 5, qq = (idx & 31) << 2;
            float4 v = *reinterpret_cast<const float4*>(
                B + (size_t)(kt * 32 + r) * 768 + n0 + qq);
            *reinterpret_cast<float4*>(&Bs[r][qq]) = cvt4(v);
        }
        __syncthreads();

#pragma unroll
        for (int kk = 0; kk < 4; kk++) {
            FragA af[4];
            FragB bf[2];
#pragma unroll
            for (int i = 0; i < 4; i++)
                wmma::load_matrix_sync(af[i], &As[wm + i * 16][kk * 8], 36);
#pragma unroll
            for (int j = 0; j < 2; j++)
                wmma::load_matrix_sync(bf[j], &Bs[kk * 8][wn + j * 16], 136);
#pragma unroll
            for (int i = 0; i < 4; i++)
#pragma unroll
                for (int j = 0; j < 2; j++)
                    wmma::mma_sync(acc[i][j], af[i], bf[j], acc[i][j]);
        }
        __syncthreads();
    }

#pragma unroll
    for (int i = 0; i < 4; i++)
#pragma unroll
        for (int j = 0; j < 2; j++)
            wmma::store_matrix_sync(&Cs[wm + i * 16][wn + j * 16], acc[i][j],
                                    132, wmma::mem_row_major);
    __syncthreads();

    {
        const int r = tid >> 1;
        const int c0 = (tid & 1) << 6;
#pragma unroll
        for (int d = 0; d < 64; d++) {
            int col = c0 + d;
            C[(size_t)(m0 + r) * 768 + n0 + col] = Cs[r][col] + bias[n0 + col];
        }
    }
}

// ---------------------------------------------------------------------------
// Orchestration
// ---------------------------------------------------------------------------
extern "C" void kernel_launch(void* const* d_in, const int* in_sizes, int n_in,
                              void* d_out, int out_size)
{
    const float* x      = (const float*)d_in[0];
    const float* W_qkv  = (const float*)d_in[1];
    const float* Wpq    = (const float*)d_in[2];
    const float* bpq    = (const float*)d_in[3];
    const float* Wpk    = (const float*)d_in[4];
    const float* bpk    = (const float*)d_in[5];
    const float* Wpv    = (const float*)d_in[6];
    const float* bpv    = (const float*)d_in[7];
    const float* g_q    = (const float*)d_in[8];
    const float* be_q   = (const float*)d_in[9];
    const float* g_k    = (const float*)d_in[10];
    const float* be_k   = (const float*)d_in[11];
    const float* g_v    = (const float*)d_in[12];
    const float* be_v   = (const float*)d_in[13];
    const float* rel    = (const float*)d_in[14];
    const float* W_proj = (const float*)d_in[15];
    const float* b_proj = (const float*)d_in[16];
    float* out = (float*)d_out;

    cudaFuncSetAttribute(qkv_pool_ln_tc,
                         cudaFuncAttributeMaxDynamicSharedMemorySize, K1_SMEM_BYTES);
    cudaFuncSetAttribute(proj_kernel,
                         cudaFuncAttributeMaxDynamicSharedMemorySize, PROJ_SMEM_BYTES);
    cudaFuncSetAttribute(attn_kernel,
                         cudaFuncAttributeMaxDynamicSharedMemorySize, ATTN_SMEM_BYTES);

    // K00: tiny Wp transpose (+ tf32 pre-round)
    transpose_wp_kernel<<<(3 * HW2 * 4096 + 255) / 256, 256>>>(Wpq, Wpk, Wpv);

    // K0: WeffT precompute (K-major store, tf32-rounded)
    weff_kernel<<<dim3(6, 3 * HW2 * NHEAD), 256>>>(W_qkv);

    // K1: fused qkv+pool GEMM + bias + LayerNorm (tcgen05 or wmma per pass)
    qkv_pool_ln_tc<<<dim3(D3 / 128, BT / 128), 256, K1_SMEM_BYTES>>>(
        x, bpq, bpk, bpv, g_q, g_k, g_v, be_q, be_k, be_v);

    // K3: attention per (b,n)
    attn_kernel<<<16 * NHEAD, 256, ATTN_SMEM_BYTES>>>(rel);

    // K4: output projection + bias
    proj_kernel<<<dim3(768 / 128, BT / 128), 256, PROJ_SMEM_BYTES>>>(
        W_proj, b_proj, out);
}